// round 16
// baseline (speedup 1.0000x reference)
#include <cuda_runtime.h>
#include <math.h>
#include <stdint.h>

typedef unsigned long long ull;

#define NTOK 4096
#define DIMF 384
#define NH   6
#define HD   64
#define NSPLIT 3          // key-tile splits: 22/21/21 of 64 tiles

// STATICS BUDGET: keep total module statics <= ~31.7 MB (proven passing).
// Crossing ~32 MiB maps a second 128 MiB arena and trips the harness guard
// (established rounds 6-9). Split 0's partial goes into d_out instead of a
// third g_po slot for exactly this reason.
__device__ float g_q[(size_t)NH * NTOK * HD];
__device__ float g_k[(size_t)NH * NTOK * HD];
__device__ float g_v[(size_t)NH * NTOK * HD];
__device__ float g_po[(size_t)2 * NH * NTOK * HD];   // splits 1,2 partials
__device__ float g_ls[(size_t)NSPLIT * NH * NTOK];   // all 3 row-sum sets

// ---------------- helpers ----------------
__device__ __forceinline__ uint32_t smem_u32(const void* p) {
    uint32_t a;
    asm("{ .reg .u64 t; cvta.to.shared.u64 t, %1; cvt.u32.u64 %0, t; }"
        : "=r"(a) : "l"(p));
    return a;
}
__device__ __forceinline__ float to_tf32(float x) {
    uint32_t r;
    asm("cvt.rna.tf32.f32 %0, %1;" : "=r"(r) : "f"(x));
    return __uint_as_float(r);
}
__device__ __forceinline__ uint32_t to_tf32_u(float x) {
    uint32_t r;
    asm("cvt.rna.tf32.f32 %0, %1;" : "=r"(r) : "f"(x));
    return r;
}
__device__ __forceinline__ void mma8(float& d0, float& d1, float& d2, float& d3,
                                     uint32_t a0, uint32_t a1, uint32_t a2, uint32_t a3,
                                     uint32_t b0, uint32_t b1) {
    asm volatile("mma.sync.aligned.m16n8k8.row.col.f32.tf32.tf32.f32 "
                 "{%0,%1,%2,%3}, {%4,%5,%6,%7}, {%8,%9}, {%0,%1,%2,%3};"
                 : "+f"(d0), "+f"(d1), "+f"(d2), "+f"(d3)
                 : "r"(a0), "r"(a1), "r"(a2), "r"(a3), "r"(b0), "r"(b1));
}
#define CP_ASYNC16(sdst, gsrc) \
    asm volatile("cp.async.cg.shared.global [%0], [%1], 16;" \
                 :: "r"(sdst), "l"(gsrc) : "memory")
#define CP_COMMIT()  asm volatile("cp.async.commit_group;" ::: "memory")
#define CP_WAIT0()   asm volatile("cp.async.wait_group 0;" ::: "memory")

// ---------------- QKV GEMM via tf32 mma.sync ----------------
// cp.async double-buffered RAW x/w staging; RNA tf32 rounding applied at
// fragment-load time (numerically identical to rounding before STS).
#define QG_STR  36
#define QG_XS0  0
#define QG_XS1  (64 * QG_STR * 4)                 // 9216
#define QG_WS0  (2 * 64 * QG_STR * 4)             // 18432
#define QG_WS1  (3 * 64 * QG_STR * 4)             // 27648
#define QG_TOTAL (4 * 64 * QG_STR * 4)            // 36864

__device__ __forceinline__ void qg_stage(uint32_t sX, uint32_t sW,
                                         const float* x, const float* w,
                                         int bm, int bj, int k0, int tid) {
    #pragma unroll
    for (int j = 0; j < 2; j++) {
        int e = tid + j * 256;                    // 512 float4s per tile
        int row = e >> 3, c4 = (e & 7) * 4;
        CP_ASYNC16(sX + (uint32_t)(row * QG_STR + c4) * 4,
                   x + (size_t)(bm + row) * DIMF + k0 + c4);
        CP_ASYNC16(sW + (uint32_t)(row * QG_STR + c4) * 4,
                   w + (size_t)(bj + row) * DIMF + k0 + c4);
    }
}

__global__ __launch_bounds__(256) void qkv_mma_kernel(
    const float* __restrict__ x, const float* __restrict__ w,
    const float* __restrict__ bias)
{
    extern __shared__ char smem[];
    const uint32_t sb = smem_u32(smem);

    const int bj = blockIdx.x * 64;
    const int bm = blockIdx.y * 64;
    const int tid  = threadIdx.x;
    const int warp = tid >> 5, lane = tid & 31;
    const int quad = lane >> 2, qq = lane & 3;
    const int wm = warp & 3, wn = warp >> 2;
    const int r0l = wm * 16 + quad;
    const int nbase = wn * 32;

    float c[4][4];
    #pragma unroll
    for (int nb = 0; nb < 4; nb++)
        c[nb][0] = c[nb][1] = c[nb][2] = c[nb][3] = 0.f;

    qg_stage(sb + QG_XS0, sb + QG_WS0, x, w, bm, bj, 0, tid);
    CP_COMMIT();

    #pragma unroll 1
    for (int ck = 0; ck < DIMF / 32; ck++) {
        const float* Xf = reinterpret_cast<const float*>(smem + ((ck & 1) ? QG_XS1 : QG_XS0));
        const float* Wf = reinterpret_cast<const float*>(smem + ((ck & 1) ? QG_WS1 : QG_WS0));
        CP_WAIT0();
        __syncthreads();          // also acts as end-of-compute barrier for ck-1
        if (ck + 1 < DIMF / 32) {
            qg_stage(sb + ((ck & 1) ? QG_XS0 : QG_XS1),
                     sb + ((ck & 1) ? QG_WS0 : QG_WS1),
                     x, w, bm, bj, (ck + 1) * 32, tid);
            CP_COMMIT();
        }

        // A fragments with RNA tf32 rounding at load
        uint32_t aa[4][4];
        #pragma unroll
        for (int ks = 0; ks < 4; ks++) {
            aa[ks][0] = to_tf32_u(Xf[r0l * QG_STR + ks * 8 + qq]);
            aa[ks][1] = to_tf32_u(Xf[(r0l + 8) * QG_STR + ks * 8 + qq]);
            aa[ks][2] = to_tf32_u(Xf[r0l * QG_STR + ks * 8 + qq + 4]);
            aa[ks][3] = to_tf32_u(Xf[(r0l + 8) * QG_STR + ks * 8 + qq + 4]);
        }
        #pragma unroll
        for (int nb = 0; nb < 4; nb++) {
            const float* wrow = Wf + (nbase + nb * 8 + quad) * QG_STR + qq;
            #pragma unroll
            for (int ks = 0; ks < 4; ks++) {
                uint32_t b0 = to_tf32_u(wrow[ks * 8]);
                uint32_t b1 = to_tf32_u(wrow[ks * 8 + 4]);
                mma8(c[nb][0], c[nb][1], c[nb][2], c[nb][3],
                     aa[ks][0], aa[ks][1], aa[ks][2], aa[ks][3], b0, b1);
            }
        }
    }

    const int sec = bj / DIMF;
    const int hh  = (bj % DIMF) >> 6;
    float* dst = (sec == 0) ? g_q : (sec == 1) ? g_k : g_v;
    const int m0 = bm + r0l;
    #pragma unroll
    for (int nb = 0; nb < 4; nb++) {
        const int col = nbase + nb * 8 + 2 * qq;
        const float b0 = __ldg(bias + bj + col);
        const float b1 = __ldg(bias + bj + col + 1);
        *reinterpret_cast<float2*>(dst + ((size_t)hh * NTOK + m0) * HD + col) =
            make_float2(to_tf32(c[nb][0] + b0), to_tf32(c[nb][1] + b1));
        *reinterpret_cast<float2*>(dst + ((size_t)hh * NTOK + m0 + 8) * HD + col) =
            make_float2(to_tf32(c[nb][2] + b0), to_tf32(c[nb][3] + b1));
    }
}

// ---------------- fused attention: tf32 mma.sync, 3-way key split ----------------
// P stays in registers (intra-quad shuffles); one barrier/tile; dist loads
// software-pipelined one nb-block ahead to hide L2 latency behind S-mma.
#define KROWS 64
#define KSTR  68
#define VSTR  72
#define SM_K0  0
#define SM_K1  (KROWS * KSTR * 4)                 // 17408
#define SM_V0  (2 * KROWS * KSTR * 4)             // 34816
#define SM_V1  (SM_V0 + KROWS * VSTR * 4)         // 53248
#define SM_RPE (SM_V1 + KROWS * VSTR * 4)         // 71680
#define SM_TOTAL (SM_RPE + 128)                   // 71808

__device__ __forceinline__ void stage_kv(uint32_t sK, uint32_t sV,
                                         const float* gk, const float* gv,
                                         int k0, int tid) {
    #pragma unroll
    for (int j = 0; j < 4; j++) {
        int e = tid + j * 256;
        int row = e >> 4, d4 = (e & 15) * 4;
        CP_ASYNC16(sK + (uint32_t)(row * KSTR + d4) * 4, gk + (size_t)(k0 + row) * HD + d4);
        CP_ASYNC16(sV + (uint32_t)(row * VSTR + d4) * 4, gv + (size_t)(k0 + row) * HD + d4);
    }
}

__global__ __launch_bounds__(256, 2) void attn_kernel(
    const int* __restrict__ dist, const float* __restrict__ rpe_table,
    float* __restrict__ out)
{
    extern __shared__ char smem[];
    const uint32_t sb = smem_u32(smem);
    float* rpe  = reinterpret_cast<float*>(smem + SM_RPE);

    const int h   = blockIdx.x;
    const int q0  = blockIdx.y * 128;
    const int spl = blockIdx.z;
    const int tstart = (spl == 0) ? 0 : (spl == 1) ? 22 : 43;
    const int ntiles = (spl == 0) ? 22 : 21;
    const int kbase  = tstart * KROWS;
    const int tid  = threadIdx.x;
    const int warp = tid >> 5, lane = tid & 31;
    const int quad = lane >> 2, qq = lane & 3;
    const int sA = (lane & 28) | (qq >> 1);       // shuffle src for P cols [0,4)
    const int sB = sA + 2;                        // shuffle src for P cols [4,8)
    const bool odd = (qq & 1);

    if (tid < 21) rpe[tid] = rpe_table[tid * NH + h];

    const float* gq = g_q + (size_t)h * NTOK * HD;
    const float* gk = g_k + (size_t)h * NTOK * HD;
    const float* gv = g_v + (size_t)h * NTOK * HD;

    const int r0l = warp * 16 + quad;
    const int r0  = q0 + r0l;

    uint32_t qa[8][4];
    #pragma unroll
    for (int ks = 0; ks < 8; ks++) {
        const float* p = gq + (size_t)r0 * HD + ks * 8 + qq;
        qa[ks][0] = __float_as_uint(p[0]);
        qa[ks][1] = __float_as_uint(p[8 * HD]);
        qa[ks][2] = __float_as_uint(p[4]);
        qa[ks][3] = __float_as_uint(p[8 * HD + 4]);
    }

    float o[8][4];
    #pragma unroll
    for (int nb = 0; nb < 8; nb++)
        o[nb][0] = o[nb][1] = o[nb][2] = o[nb][3] = 0.f;
    float ls0 = 0.f, ls1 = 0.f;

    const int* dr0 = dist + (size_t)r0 * NTOK;
    const int* dr1 = dr0 + 8 * NTOK;

    stage_kv(sb + SM_K0, sb + SM_V0, gk, gv, kbase, tid);
    CP_COMMIT();

    #pragma unroll 1
    for (int kt = 0; kt < ntiles; kt++) {
        const int k0 = kbase + kt * KROWS;
        const float* Kf = reinterpret_cast<const float*>(smem + ((kt & 1) ? SM_K1 : SM_K0));
        const float* Vf = reinterpret_cast<const float*>(smem + ((kt & 1) ? SM_V1 : SM_V0));

        CP_WAIT0();
        __syncthreads();          // single barrier per tile

        if (kt + 1 < ntiles) {    // stage next tile into the other buffers now
            stage_kv(sb + ((kt & 1) ? SM_K0 : SM_K1),
                     sb + ((kt & 1) ? SM_V0 : SM_V1), gk, gv, k0 + KROWS, tid);
            CP_COMMIT();
        }

        const uint32_t* Vu = reinterpret_cast<const uint32_t*>(Vf);

        // dist pipeline: prefetch block 0 now, block nb+1 during block nb
        int2 dc0 = *reinterpret_cast<const int2*>(dr0 + k0 + 2 * qq);
        int2 dc1 = *reinterpret_cast<const int2*>(dr1 + k0 + 2 * qq);

        #pragma unroll
        for (int nb = 0; nb < 8; nb++) {
            int2 dn0, dn1;
            if (nb < 7) {
                dn0 = *reinterpret_cast<const int2*>(dr0 + k0 + (nb + 1) * 8 + 2 * qq);
                dn1 = *reinterpret_cast<const int2*>(dr1 + k0 + (nb + 1) * 8 + 2 * qq);
            } else {
                dn0 = dc0; dn1 = dc1;
            }
            // ---- S = Q K^T: two independent 4-deep mma chains ----
            float sa0 = 0.f, sa1 = 0.f, sa2 = 0.f, sa3 = 0.f;
            float sb0 = 0.f, sb1 = 0.f, sb2 = 0.f, sb3 = 0.f;
            const uint32_t* krow0 = reinterpret_cast<const uint32_t*>(
                Kf + (nb * 8 + quad) * KSTR + qq);
            #pragma unroll
            for (int ks = 0; ks < 4; ks++) {
                uint32_t b0 = krow0[ks * 8];
                uint32_t b1 = krow0[ks * 8 + 4];
                mma8(sa0, sa1, sa2, sa3, qa[ks][0], qa[ks][1], qa[ks][2], qa[ks][3], b0, b1);
                uint32_t c0 = krow0[(ks + 4) * 8];
                uint32_t c1 = krow0[(ks + 4) * 8 + 4];
                mma8(sb0, sb1, sb2, sb3, qa[ks+4][0], qa[ks+4][1], qa[ks+4][2], qa[ks+4][3], c0, c1);
            }
            float s0 = sa0 + sb0, s1 = sa1 + sb1;
            float s2 = sa2 + sb2, s3 = sa3 + sb3;
            // ---- rpe bias + exp (no-max softmax), dist from pipeline regs ----
            int t0 = min(max(dc0.x, 0), 20), t1 = min(max(dc0.y, 0), 20);
            int t2 = min(max(dc1.x, 0), 20), t3 = min(max(dc1.y, 0), 20);
            float p0 = __expf(s0 + rpe[t0]);
            float p1 = __expf(s1 + rpe[t1]);
            float p2 = __expf(s2 + rpe[t2]);
            float p3 = __expf(s3 + rpe[t3]);
            ls0 += p0 + p1;
            ls1 += p2 + p3;
            p0 = to_tf32(p0); p1 = to_tf32(p1);
            p2 = to_tf32(p2); p3 = to_tf32(p3);
            dc0 = dn0; dc1 = dn1;

            // ---- accumulator layout -> A-fragment layout (intra-quad shuffles) ----
            float g0 = __shfl_sync(0xffffffffu, p0, sA);
            float g1 = __shfl_sync(0xffffffffu, p1, sA);
            float h0 = __shfl_sync(0xffffffffu, p0, sB);
            float h1 = __shfl_sync(0xffffffffu, p1, sB);
            uint32_t pa0 = __float_as_uint(odd ? g1 : g0);   // P(r,   qq)
            uint32_t pa2 = __float_as_uint(odd ? h1 : h0);   // P(r,   qq+4)
            float g2 = __shfl_sync(0xffffffffu, p2, sA);
            float g3 = __shfl_sync(0xffffffffu, p3, sA);
            float h2 = __shfl_sync(0xffffffffu, p2, sB);
            float h3 = __shfl_sync(0xffffffffu, p3, sB);
            uint32_t pa1 = __float_as_uint(odd ? g3 : g2);   // P(r+8, qq)
            uint32_t pa3 = __float_as_uint(odd ? h3 : h2);   // P(r+8, qq+4)

            // ---- O += P(block nb) * V(block nb) ----
            const uint32_t* vrow0 = Vu + (nb * 8 + qq) * VSTR + quad;
            const uint32_t* vrow1 = Vu + (nb * 8 + qq + 4) * VSTR + quad;
            #pragma unroll
            for (int j = 0; j < 8; j++) {
                uint32_t b0 = vrow0[j * 8];
                uint32_t b1 = vrow1[j * 8];
                mma8(o[j][0], o[j][1], o[j][2], o[j][3], pa0, pa1, pa2, pa3, b0, b1);
            }
        }
    }

    ls0 += __shfl_xor_sync(0xffffffffu, ls0, 1);
    ls0 += __shfl_xor_sync(0xffffffffu, ls0, 2);
    ls1 += __shfl_xor_sync(0xffffffffu, ls1, 1);
    ls1 += __shfl_xor_sync(0xffffffffu, ls1, 2);

    if (qq == 0) {
        g_ls[(size_t)(spl * NH + h) * NTOK + r0]     = ls0;
        g_ls[(size_t)(spl * NH + h) * NTOK + r0 + 8] = ls1;
    }
    if (spl == 0) {
        float* op0 = out + (size_t)r0 * DIMF + h * HD;
        float* op1 = op0 + (size_t)8 * DIMF;
        #pragma unroll
        for (int nb = 0; nb < 8; nb++) {
            *reinterpret_cast<float2*>(op0 + nb * 8 + 2 * qq) =
                make_float2(o[nb][0], o[nb][1]);
            *reinterpret_cast<float2*>(op1 + nb * 8 + 2 * qq) =
                make_float2(o[nb][2], o[nb][3]);
        }
    } else {
        const size_t pbase = ((size_t)((spl - 1) * NH + h) * NTOK + r0) * HD;
        #pragma unroll
        for (int nb = 0; nb < 8; nb++) {
            *reinterpret_cast<float2*>(g_po + pbase + nb * 8 + 2 * qq) =
                make_float2(o[nb][0], o[nb][1]);
            *reinterpret_cast<float2*>(g_po + pbase + 8 * HD + nb * 8 + 2 * qq) =
                make_float2(o[nb][2], o[nb][3]);
        }
    }
}

// ---------------- combine: out = (out + po0 + po1) / (l0+l1+l2) ----------------
__global__ __launch_bounds__(256) void combine_kernel(float* __restrict__ out) {
    const int idx = blockIdx.x * 256 + threadIdx.x;
    const int total4 = NTOK * DIMF / 4;
    if (idx >= total4) return;
    const int row = idx / (DIMF / 4);
    const int col = (idx % (DIMF / 4)) * 4;
    const int h = col >> 6, d = col & 63;

    const size_t p0 = ((size_t)h * NTOK + row) * HD + d;
    const size_t p1 = ((size_t)(NH + h) * NTOK + row) * HD + d;
    float4 a = *reinterpret_cast<const float4*>(out + (size_t)row * DIMF + col);
    float4 b = *reinterpret_cast<const float4*>(g_po + p0);
    float4 c = *reinterpret_cast<const float4*>(g_po + p1);
    float l = g_ls[(size_t)h * NTOK + row]
            + g_ls[(size_t)(NH + h) * NTOK + row]
            + g_ls[(size_t)(2 * NH + h) * NTOK + row];
    const float inv = 1.0f / l;
    *reinterpret_cast<float4*>(out + (size_t)row * DIMF + col) =
        make_float4((a.x + b.x + c.x) * inv, (a.y + b.y + c.y) * inv,
                    (a.z + b.z + c.z) * inv, (a.w + b.w + c.w) * inv);
}

extern "C" void kernel_launch(void* const* d_in, const int* in_sizes, int n_in,
                              void* d_out, int out_size) {
    const float* x    = (const float*)d_in[0];   // (1,4096,384)
    const int*   dist = (const int*)  d_in[1];   // (1,4096,4096)
    const float* w    = (const float*)d_in[2];   // (1152,384)
    const float* b    = (const float*)d_in[3];   // (1152,)
    const float* rpe  = (const float*)d_in[4];   // (21,6)
    float* out = (float*)d_out;                  // (1,4096,384)

    qkv_mma_kernel<<<dim3(1152/64, 4096/64), 256, QG_TOTAL>>>(x, w, b);

    cudaFuncSetAttribute(attn_kernel,
                         cudaFuncAttributeMaxDynamicSharedMemorySize, SM_TOTAL);
    attn_kernel<<<dim3(NH, NTOK/128, NSPLIT), 256, SM_TOTAL>>>(dist, rpe, out);

    combine_kernel<<<(NTOK * DIMF / 4 + 255) / 256, 256>>>(out);
}

// round 17
// speedup vs baseline: 1.0215x; 1.0215x over previous
#include <cuda_runtime.h>
#include <math.h>
#include <stdint.h>

typedef unsigned long long ull;

#define NTOK 4096
#define DIMF 384
#define NH   6
#define HD   64
#define NSPLIT 3          // key-tile splits: 22/21/21 of 64 tiles

// STATICS BUDGET: keep total module statics <= ~31.7 MB (proven passing).
// Crossing ~32 MiB maps a second 128 MiB arena and trips the harness guard
// (established rounds 6-9). Split 0's partial goes into d_out instead of a
// third g_po slot for exactly this reason.
__device__ float g_q[(size_t)NH * NTOK * HD];
__device__ float g_k[(size_t)NH * NTOK * HD];
__device__ float g_v[(size_t)NH * NTOK * HD];
__device__ float g_po[(size_t)2 * NH * NTOK * HD];   // splits 1,2 partials
__device__ float g_ls[(size_t)NSPLIT * NH * NTOK];   // all 3 row-sum sets

// ---------------- helpers ----------------
__device__ __forceinline__ uint32_t smem_u32(const void* p) {
    uint32_t a;
    asm("{ .reg .u64 t; cvta.to.shared.u64 t, %1; cvt.u32.u64 %0, t; }"
        : "=r"(a) : "l"(p));
    return a;
}
__device__ __forceinline__ float to_tf32(float x) {
    uint32_t r;
    asm("cvt.rna.tf32.f32 %0, %1;" : "=r"(r) : "f"(x));
    return __uint_as_float(r);
}
__device__ __forceinline__ uint32_t to_tf32_u(float x) {
    uint32_t r;
    asm("cvt.rna.tf32.f32 %0, %1;" : "=r"(r) : "f"(x));
    return r;
}
__device__ __forceinline__ void mma8(float& d0, float& d1, float& d2, float& d3,
                                     uint32_t a0, uint32_t a1, uint32_t a2, uint32_t a3,
                                     uint32_t b0, uint32_t b1) {
    asm volatile("mma.sync.aligned.m16n8k8.row.col.f32.tf32.tf32.f32 "
                 "{%0,%1,%2,%3}, {%4,%5,%6,%7}, {%8,%9}, {%0,%1,%2,%3};"
                 : "+f"(d0), "+f"(d1), "+f"(d2), "+f"(d3)
                 : "r"(a0), "r"(a1), "r"(a2), "r"(a3), "r"(b0), "r"(b1));
}
#define CP_ASYNC16(sdst, gsrc) \
    asm volatile("cp.async.cg.shared.global [%0], [%1], 16;" \
                 :: "r"(sdst), "l"(gsrc) : "memory")
#define CP_COMMIT()  asm volatile("cp.async.commit_group;" ::: "memory")
#define CP_WAIT0()   asm volatile("cp.async.wait_group 0;" ::: "memory")

// ---------------- QKV GEMM via tf32 mma.sync, 128m x 64n CTA tile ----------------
// cp.async double-buffered raw x/w; RNA tf32 rounding at fragment load.
// 8 warps x 16 rows, each warp covers all 64 cols (c[8][4], attn-proven layout).
#define QG_STR  36
#define QG_XS0  0
#define QG_XS1  (128 * QG_STR * 4)                // 18432
#define QG_WS0  (2 * 128 * QG_STR * 4)            // 36864
#define QG_WS1  (QG_WS0 + 64 * QG_STR * 4)        // 46080
#define QG_TOTAL (QG_WS1 + 64 * QG_STR * 4)       // 55296

__device__ __forceinline__ void qg_stage(uint32_t sX, uint32_t sW,
                                         const float* x, const float* w,
                                         int bm, int bj, int k0, int tid) {
    #pragma unroll
    for (int j = 0; j < 4; j++) {                 // X: 128 rows x 8 float4
        int e = tid + j * 256;
        int row = e >> 3, c4 = (e & 7) * 4;
        CP_ASYNC16(sX + (uint32_t)(row * QG_STR + c4) * 4,
                   x + (size_t)(bm + row) * DIMF + k0 + c4);
    }
    #pragma unroll
    for (int j = 0; j < 2; j++) {                 // W: 64 rows x 8 float4
        int e = tid + j * 256;
        int row = e >> 3, c4 = (e & 7) * 4;
        CP_ASYNC16(sW + (uint32_t)(row * QG_STR + c4) * 4,
                   w + (size_t)(bj + row) * DIMF + k0 + c4);
    }
}

__global__ __launch_bounds__(256) void qkv_mma_kernel(
    const float* __restrict__ x, const float* __restrict__ w,
    const float* __restrict__ bias)
{
    extern __shared__ char smem[];
    const uint32_t sb = smem_u32(smem);

    const int bj = blockIdx.x * 64;
    const int bm = blockIdx.y * 128;
    const int tid  = threadIdx.x;
    const int warp = tid >> 5, lane = tid & 31;
    const int quad = lane >> 2, qq = lane & 3;
    const int r0l = warp * 16 + quad;             // row in [0,128)

    float c[8][4];
    #pragma unroll
    for (int nb = 0; nb < 8; nb++)
        c[nb][0] = c[nb][1] = c[nb][2] = c[nb][3] = 0.f;

    qg_stage(sb + QG_XS0, sb + QG_WS0, x, w, bm, bj, 0, tid);
    CP_COMMIT();

    #pragma unroll 1
    for (int ck = 0; ck < DIMF / 32; ck++) {
        const float* Xf = reinterpret_cast<const float*>(smem + ((ck & 1) ? QG_XS1 : QG_XS0));
        const float* Wf = reinterpret_cast<const float*>(smem + ((ck & 1) ? QG_WS1 : QG_WS0));
        CP_WAIT0();
        __syncthreads();
        if (ck + 1 < DIMF / 32) {
            qg_stage(sb + ((ck & 1) ? QG_XS0 : QG_XS1),
                     sb + ((ck & 1) ? QG_WS0 : QG_WS1),
                     x, w, bm, bj, (ck + 1) * 32, tid);
            CP_COMMIT();
        }

        // A fragments (RNA tf32 at load), reused across all 8 nb blocks
        uint32_t aa[4][4];
        #pragma unroll
        for (int ks = 0; ks < 4; ks++) {
            aa[ks][0] = to_tf32_u(Xf[r0l * QG_STR + ks * 8 + qq]);
            aa[ks][1] = to_tf32_u(Xf[(r0l + 8) * QG_STR + ks * 8 + qq]);
            aa[ks][2] = to_tf32_u(Xf[r0l * QG_STR + ks * 8 + qq + 4]);
            aa[ks][3] = to_tf32_u(Xf[(r0l + 8) * QG_STR + ks * 8 + qq + 4]);
        }
        #pragma unroll
        for (int nb = 0; nb < 8; nb++) {
            const float* wrow = Wf + (nb * 8 + quad) * QG_STR + qq;
            #pragma unroll
            for (int ks = 0; ks < 4; ks++) {
                uint32_t b0 = to_tf32_u(wrow[ks * 8]);
                uint32_t b1 = to_tf32_u(wrow[ks * 8 + 4]);
                mma8(c[nb][0], c[nb][1], c[nb][2], c[nb][3],
                     aa[ks][0], aa[ks][1], aa[ks][2], aa[ks][3], b0, b1);
            }
        }
    }

    const int sec = bj / DIMF;                    // 0=Q 1=K 2=V, uniform per CTA
    const int hh  = (bj % DIMF) >> 6;
    float* dst = (sec == 0) ? g_q : (sec == 1) ? g_k : g_v;
    const int m0 = bm + r0l;
    #pragma unroll
    for (int nb = 0; nb < 8; nb++) {
        const int col = nb * 8 + 2 * qq;
        const float b0 = __ldg(bias + bj + col);
        const float b1 = __ldg(bias + bj + col + 1);
        *reinterpret_cast<float2*>(dst + ((size_t)hh * NTOK + m0) * HD + col) =
            make_float2(to_tf32(c[nb][0] + b0), to_tf32(c[nb][1] + b1));
        *reinterpret_cast<float2*>(dst + ((size_t)hh * NTOK + m0 + 8) * HD + col) =
            make_float2(to_tf32(c[nb][2] + b0), to_tf32(c[nb][3] + b1));
    }
}

// ---------------- fused attention: tf32 mma.sync, 3-way key split ----------------
// P stays in registers (intra-quad shuffles); one barrier/tile; dist loads
// software-pipelined one nb-block ahead.
#define KROWS 64
#define KSTR  68
#define VSTR  72
#define SM_K0  0
#define SM_K1  (KROWS * KSTR * 4)                 // 17408
#define SM_V0  (2 * KROWS * KSTR * 4)             // 34816
#define SM_V1  (SM_V0 + KROWS * VSTR * 4)         // 53248
#define SM_RPE (SM_V1 + KROWS * VSTR * 4)         // 71680
#define SM_TOTAL (SM_RPE + 128)                   // 71808

__device__ __forceinline__ void stage_kv(uint32_t sK, uint32_t sV,
                                         const float* gk, const float* gv,
                                         int k0, int tid) {
    #pragma unroll
    for (int j = 0; j < 4; j++) {
        int e = tid + j * 256;
        int row = e >> 4, d4 = (e & 15) * 4;
        CP_ASYNC16(sK + (uint32_t)(row * KSTR + d4) * 4, gk + (size_t)(k0 + row) * HD + d4);
        CP_ASYNC16(sV + (uint32_t)(row * VSTR + d4) * 4, gv + (size_t)(k0 + row) * HD + d4);
    }
}

__global__ __launch_bounds__(256, 2) void attn_kernel(
    const int* __restrict__ dist, const float* __restrict__ rpe_table,
    float* __restrict__ out)
{
    extern __shared__ char smem[];
    const uint32_t sb = smem_u32(smem);
    float* rpe  = reinterpret_cast<float*>(smem + SM_RPE);

    const int h   = blockIdx.x;
    const int q0  = blockIdx.y * 128;
    const int spl = blockIdx.z;
    const int tstart = (spl == 0) ? 0 : (spl == 1) ? 22 : 43;
    const int ntiles = (spl == 0) ? 22 : 21;
    const int kbase  = tstart * KROWS;
    const int tid  = threadIdx.x;
    const int warp = tid >> 5, lane = tid & 31;
    const int quad = lane >> 2, qq = lane & 3;
    const int sA = (lane & 28) | (qq >> 1);       // shuffle src for P cols [0,4)
    const int sB = sA + 2;                        // shuffle src for P cols [4,8)
    const bool odd = (qq & 1);

    if (tid < 21) rpe[tid] = rpe_table[tid * NH + h];

    const float* gq = g_q + (size_t)h * NTOK * HD;
    const float* gk = g_k + (size_t)h * NTOK * HD;
    const float* gv = g_v + (size_t)h * NTOK * HD;

    const int r0l = warp * 16 + quad;
    const int r0  = q0 + r0l;

    uint32_t qa[8][4];
    #pragma unroll
    for (int ks = 0; ks < 8; ks++) {
        const float* p = gq + (size_t)r0 * HD + ks * 8 + qq;
        qa[ks][0] = __float_as_uint(p[0]);
        qa[ks][1] = __float_as_uint(p[8 * HD]);
        qa[ks][2] = __float_as_uint(p[4]);
        qa[ks][3] = __float_as_uint(p[8 * HD + 4]);
    }

    float o[8][4];
    #pragma unroll
    for (int nb = 0; nb < 8; nb++)
        o[nb][0] = o[nb][1] = o[nb][2] = o[nb][3] = 0.f;
    float ls0 = 0.f, ls1 = 0.f;

    const int* dr0 = dist + (size_t)r0 * NTOK;
    const int* dr1 = dr0 + 8 * NTOK;

    stage_kv(sb + SM_K0, sb + SM_V0, gk, gv, kbase, tid);
    CP_COMMIT();

    #pragma unroll 1
    for (int kt = 0; kt < ntiles; kt++) {
        const int k0 = kbase + kt * KROWS;
        const float* Kf = reinterpret_cast<const float*>(smem + ((kt & 1) ? SM_K1 : SM_K0));
        const float* Vf = reinterpret_cast<const float*>(smem + ((kt & 1) ? SM_V1 : SM_V0));

        CP_WAIT0();
        __syncthreads();          // single barrier per tile

        if (kt + 1 < ntiles) {    // stage next tile into the other buffers now
            stage_kv(sb + ((kt & 1) ? SM_K0 : SM_K1),
                     sb + ((kt & 1) ? SM_V0 : SM_V1), gk, gv, k0 + KROWS, tid);
            CP_COMMIT();
        }

        const uint32_t* Vu = reinterpret_cast<const uint32_t*>(Vf);

        // dist pipeline: prefetch block 0 now, block nb+1 during block nb
        int2 dc0 = *reinterpret_cast<const int2*>(dr0 + k0 + 2 * qq);
        int2 dc1 = *reinterpret_cast<const int2*>(dr1 + k0 + 2 * qq);

        #pragma unroll
        for (int nb = 0; nb < 8; nb++) {
            int2 dn0, dn1;
            if (nb < 7) {
                dn0 = *reinterpret_cast<const int2*>(dr0 + k0 + (nb + 1) * 8 + 2 * qq);
                dn1 = *reinterpret_cast<const int2*>(dr1 + k0 + (nb + 1) * 8 + 2 * qq);
            } else {
                dn0 = dc0; dn1 = dc1;
            }
            // ---- S = Q K^T: two independent 4-deep mma chains ----
            float sa0 = 0.f, sa1 = 0.f, sa2 = 0.f, sa3 = 0.f;
            float sb0 = 0.f, sb1 = 0.f, sb2 = 0.f, sb3 = 0.f;
            const uint32_t* krow0 = reinterpret_cast<const uint32_t*>(
                Kf + (nb * 8 + quad) * KSTR + qq);
            #pragma unroll
            for (int ks = 0; ks < 4; ks++) {
                uint32_t b0 = krow0[ks * 8];
                uint32_t b1 = krow0[ks * 8 + 4];
                mma8(sa0, sa1, sa2, sa3, qa[ks][0], qa[ks][1], qa[ks][2], qa[ks][3], b0, b1);
                uint32_t c0 = krow0[(ks + 4) * 8];
                uint32_t c1 = krow0[(ks + 4) * 8 + 4];
                mma8(sb0, sb1, sb2, sb3, qa[ks+4][0], qa[ks+4][1], qa[ks+4][2], qa[ks+4][3], c0, c1);
            }
            float s0 = sa0 + sb0, s1 = sa1 + sb1;
            float s2 = sa2 + sb2, s3 = sa3 + sb3;
            // ---- rpe bias + exp (no-max softmax), dist from pipeline regs ----
            int t0 = min(max(dc0.x, 0), 20), t1 = min(max(dc0.y, 0), 20);
            int t2 = min(max(dc1.x, 0), 20), t3 = min(max(dc1.y, 0), 20);
            float p0 = __expf(s0 + rpe[t0]);
            float p1 = __expf(s1 + rpe[t1]);
            float p2 = __expf(s2 + rpe[t2]);
            float p3 = __expf(s3 + rpe[t3]);
            ls0 += p0 + p1;
            ls1 += p2 + p3;
            p0 = to_tf32(p0); p1 = to_tf32(p1);
            p2 = to_tf32(p2); p3 = to_tf32(p3);
            dc0 = dn0; dc1 = dn1;

            // ---- accumulator layout -> A-fragment layout (intra-quad shuffles) ----
            float g0 = __shfl_sync(0xffffffffu, p0, sA);
            float g1 = __shfl_sync(0xffffffffu, p1, sA);
            float h0 = __shfl_sync(0xffffffffu, p0, sB);
            float h1 = __shfl_sync(0xffffffffu, p1, sB);
            uint32_t pa0 = __float_as_uint(odd ? g1 : g0);   // P(r,   qq)
            uint32_t pa2 = __float_as_uint(odd ? h1 : h0);   // P(r,   qq+4)
            float g2 = __shfl_sync(0xffffffffu, p2, sA);
            float g3 = __shfl_sync(0xffffffffu, p3, sA);
            float h2 = __shfl_sync(0xffffffffu, p2, sB);
            float h3 = __shfl_sync(0xffffffffu, p3, sB);
            uint32_t pa1 = __float_as_uint(odd ? g3 : g2);   // P(r+8, qq)
            uint32_t pa3 = __float_as_uint(odd ? h3 : h2);   // P(r+8, qq+4)

            // ---- O += P(block nb) * V(block nb) ----
            const uint32_t* vrow0 = Vu + (nb * 8 + qq) * VSTR + quad;
            const uint32_t* vrow1 = Vu + (nb * 8 + qq + 4) * VSTR + quad;
            #pragma unroll
            for (int j = 0; j < 8; j++) {
                uint32_t b0 = vrow0[j * 8];
                uint32_t b1 = vrow1[j * 8];
                mma8(o[j][0], o[j][1], o[j][2], o[j][3], pa0, pa1, pa2, pa3, b0, b1);
            }
        }
    }

    ls0 += __shfl_xor_sync(0xffffffffu, ls0, 1);
    ls0 += __shfl_xor_sync(0xffffffffu, ls0, 2);
    ls1 += __shfl_xor_sync(0xffffffffu, ls1, 1);
    ls1 += __shfl_xor_sync(0xffffffffu, ls1, 2);

    if (qq == 0) {
        g_ls[(size_t)(spl * NH + h) * NTOK + r0]     = ls0;
        g_ls[(size_t)(spl * NH + h) * NTOK + r0 + 8] = ls1;
    }
    if (spl == 0) {
        float* op0 = out + (size_t)r0 * DIMF + h * HD;
        float* op1 = op0 + (size_t)8 * DIMF;
        #pragma unroll
        for (int nb = 0; nb < 8; nb++) {
            *reinterpret_cast<float2*>(op0 + nb * 8 + 2 * qq) =
                make_float2(o[nb][0], o[nb][1]);
            *reinterpret_cast<float2*>(op1 + nb * 8 + 2 * qq) =
                make_float2(o[nb][2], o[nb][3]);
        }
    } else {
        const size_t pbase = ((size_t)((spl - 1) * NH + h) * NTOK + r0) * HD;
        #pragma unroll
        for (int nb = 0; nb < 8; nb++) {
            *reinterpret_cast<float2*>(g_po + pbase + nb * 8 + 2 * qq) =
                make_float2(o[nb][0], o[nb][1]);
            *reinterpret_cast<float2*>(g_po + pbase + 8 * HD + nb * 8 + 2 * qq) =
                make_float2(o[nb][2], o[nb][3]);
        }
    }
}

// ---------------- combine: out = (out + po0 + po1) / (l0+l1+l2) ----------------
__global__ __launch_bounds__(256) void combine_kernel(float* __restrict__ out) {
    const int idx = blockIdx.x * 256 + threadIdx.x;
    const int total4 = NTOK * DIMF / 4;
    if (idx >= total4) return;
    const int row = idx / (DIMF / 4);
    const int col = (idx % (DIMF / 4)) * 4;
    const int h = col >> 6, d = col & 63;

    const size_t p0 = ((size_t)h * NTOK + row) * HD + d;
    const size_t p1 = ((size_t)(NH + h) * NTOK + row) * HD + d;
    float4 a = *reinterpret_cast<const float4*>(out + (size_t)row * DIMF + col);
    float4 b = *reinterpret_cast<const float4*>(g_po + p0);
    float4 c = *reinterpret_cast<const float4*>(g_po + p1);
    float l = g_ls[(size_t)h * NTOK + row]
            + g_ls[(size_t)(NH + h) * NTOK + row]
            + g_ls[(size_t)(2 * NH + h) * NTOK + row];
    const float inv = 1.0f / l;
    *reinterpret_cast<float4*>(out + (size_t)row * DIMF + col) =
        make_float4((a.x + b.x + c.x) * inv, (a.y + b.y + c.y) * inv,
                    (a.z + b.z + c.z) * inv, (a.w + b.w + c.w) * inv);
}

extern "C" void kernel_launch(void* const* d_in, const int* in_sizes, int n_in,
                              void* d_out, int out_size) {
    const float* x    = (const float*)d_in[0];   // (1,4096,384)
    const int*   dist = (const int*)  d_in[1];   // (1,4096,4096)
    const float* w    = (const float*)d_in[2];   // (1152,384)
    const float* b    = (const float*)d_in[3];   // (1152,)
    const float* rpe  = (const float*)d_in[4];   // (21,6)
    float* out = (float*)d_out;                  // (1,4096,384)

    cudaFuncSetAttribute(qkv_mma_kernel,
                         cudaFuncAttributeMaxDynamicSharedMemorySize, QG_TOTAL);
    qkv_mma_kernel<<<dim3(1152/64, 4096/128), 256, QG_TOTAL>>>(x, w, b);

    cudaFuncSetAttribute(attn_kernel,
                         cudaFuncAttributeMaxDynamicSharedMemorySize, SM_TOTAL);
    attn_kernel<<<dim3(NH, NTOK/128, NSPLIT), 256, SM_TOTAL>>>(dist, rpe, out);

    combine_kernel<<<(NTOK * DIMF / 4 + 255) / 256, 256>>>(out);
}